// round 17
// baseline (speedup 1.0000x reference)
#include <cuda_runtime.h>
#include <cuda_fp16.h>
#include <cuda_bf16.h>

#define TT 12
#define CC 32
#define MAXN 131072

// ---- bit-cast helpers ----
__device__ __forceinline__ unsigned h2_as_u32(__half2 h) {
    union { __half2 h; unsigned u; } cvt; cvt.h = h; return cvt.u;
}
__device__ __forceinline__ __half2 u32_as_h2(unsigned u) {
    union { unsigned u; __half2 h; } cvt; cvt.u = u; return cvt.h;
}

// ---- scratch (device globals; zero-init at load; kept zeroed by k_final) ----
__device__ float g_deg[MAXN];                    // Σ incoming w; re-zeroed by k_final
__device__ float g_dinv[MAXN];
__device__ __align__(128) uint4 g_yh[MAXN * 2];  // f16 y rows: 16 halves (12 used) = 32B
__device__ __align__(128) uint4 g_aggh[MAXN * 2];// f16 agg rows: 16 halves (12 used) = 32B; re-zeroed
__device__ __half2 g_hz_a[CC], g_hz_b[CC];       // broadcast half2: az/2, bz/2
__device__ __half2 g_hh_a[CC], g_hh_b[CC];       // broadcast half2: ah, bh
__device__ __half2 g_p2[TT / 2];                 // probs (0.5*softmax) as t-pairs
__device__ float g_hw[CC];
__device__ float g_hb;

__device__ __forceinline__ unsigned tanh2_fast(unsigned x) {  // tanh.approx on a half2 pair
    unsigned y;
    asm("tanh.approx.f16x2 %0, %1;" : "=r"(y) : "r"(x));
    return y;
}

// f16x2 vector reduction: 8 halves (16B) per op — .v4 is the ptxas max
__device__ __forceinline__ void red4h2(unsigned* p, unsigned a, unsigned b, unsigned c, unsigned d) {
    asm volatile("red.global.add.noftz.v4.f16x2 [%0], {%1, %2, %3, %4};"
                 :: "l"(p), "r"(a), "r"(b), "r"(c), "r"(d) : "memory");
}

// ---- K1: deg accumulation (blocks [0, degBlocks)) + consts fold (block degBlocks) ----
__global__ void k_deg_consts(const int* __restrict__ ei, const float* __restrict__ ew, int e,
                             int degBlocks,
                             const float* __restrict__ w_z, const float* __restrict__ b_z,
                             const float* __restrict__ w_h, const float* __restrict__ b_h,
                             const float* __restrict__ lw_z, const float* __restrict__ lb_z,
                             const float* __restrict__ lw_h, const float* __restrict__ lb_h,
                             const float* __restrict__ att,
                             const float* __restrict__ head_w, const float* __restrict__ head_b) {
#if __CUDA_ARCH__ >= 900
    cudaTriggerProgrammaticLaunchCompletion();   // let the next kernel dispatch early
#endif
    if (blockIdx.x < (unsigned)degBlocks) {
        int base = (blockIdx.x * blockDim.x + threadIdx.x) * 4;
        if (base + 3 < e) {
            int4   d = *reinterpret_cast<const int4*>(ei + e + base);
            float4 w = *reinterpret_cast<const float4*>(ew + base);
            atomicAdd(&g_deg[d.x], w.x);
            atomicAdd(&g_deg[d.y], w.y);
            atomicAdd(&g_deg[d.z], w.z);
            atomicAdd(&g_deg[d.w], w.w);
        } else {
            for (int i = base; i < e; i++) atomicAdd(&g_deg[ei[e + i]], ew[i]);
        }
        return;
    }
    // ---- consts block ----
    int o = threadIdx.x;
    if (o < CC) {
        float az = 0.f, bz = 0.f, ah = 0.f, bh = 0.f;
        const float* rz = lw_z + o * 2 * CC;   // torch layout [C, 2C]; first C cols used
        const float* rh = lw_h + o * 2 * CC;
        #pragma unroll
        for (int c = 0; c < CC; c++) {
            az += w_z[c] * rz[c];
            bz += b_z[c] * rz[c];
            ah += w_h[c] * rh[c];
            bh += b_h[c] * rh[c];
        }
        g_hz_a[o] = __float2half2_rn(0.5f * az);
        g_hz_b[o] = __float2half2_rn(0.5f * (bz + lb_z[o]));
        g_hh_a[o] = __float2half2_rn(ah);
        g_hh_b[o] = __float2half2_rn(bh + lb_h[o]);
        g_hw[o] = head_w[o];
    }
    if (o == 0) {
        float m = -1e30f;
        for (int t = 0; t < TT; t++) m = fmaxf(m, att[t]);
        float ex[TT]; float sum = 0.f;
        for (int t = 0; t < TT; t++) { ex[t] = expf(att[t] - m); sum += ex[t]; }
        float inv = 0.5f / sum;                 // fold the 0.5 of (1-z)
        for (int t = 0; t < TT / 2; t++)
            g_p2[t] = __floats2half2_rn(ex[2 * t] * inv, ex[2 * t + 1] * inv);
        g_hb = head_b[0];
    }
}

// ---- K2: dinv + f16 y row (32B, 12 of 16 halves used) ; one thread per node ----
// PDL: preload x row (external input), then wait for deg.
__global__ void k_dinv_y(const float* __restrict__ x, int n) {
    int i = blockIdx.x * blockDim.x + threadIdx.x;
    float4 v0, v1, v2;
    if (i < n) {
        const float4* xr = reinterpret_cast<const float4*>(x + (size_t)i * TT);
        v0 = __ldg(xr + 0); v1 = __ldg(xr + 1); v2 = __ldg(xr + 2);
    }
#if __CUDA_ARCH__ >= 900
    cudaTriggerProgrammaticLaunchCompletion();
    cudaGridDependencySynchronize();            // deg ready
#endif
    if (i >= n) return;
    float di = rsqrtf(1.0f + g_deg[i]);   // +1 = self-loop weight; always > 0
    g_dinv[i] = di;
    uint4 a, b;
    a.x = h2_as_u32(__floats2half2_rn(di * v0.x, di * v0.y));
    a.y = h2_as_u32(__floats2half2_rn(di * v0.z, di * v0.w));
    a.z = h2_as_u32(__floats2half2_rn(di * v1.x, di * v1.y));
    a.w = h2_as_u32(__floats2half2_rn(di * v1.z, di * v1.w));
    b.x = h2_as_u32(__floats2half2_rn(di * v2.x, di * v2.y));
    b.y = h2_as_u32(__floats2half2_rn(di * v2.z, di * v2.w));
    b.z = 0u; b.w = 0u;                   // pad halves 12..15 (stay zero through REDs)
    g_yh[(size_t)i * 2 + 0] = a;
    g_yh[(size_t)i * 2 + 1] = b;
}

// ---- K3: 1-thread-per-edge scatter  aggh[d,:] += w * yh[s,:]  (2× v4.f16x2 RED) ----
// Index loads once per edge (12B, not duplicated across lanes); gather 2 LDG.128
// of one 32B sector; pad halves in v1.z/.w are zero in y so their REDs add 0.
__global__ void k_scatter1(const int* __restrict__ ei, const float* __restrict__ ew, int e) {
    int i = blockIdx.x * blockDim.x + threadIdx.x;
    int s = 0, d = 0; float w = 0.f;
    bool act = i < e;
    if (act) {
        s = __ldg(ei + i);
        d = __ldg(ei + e + i);
        w = __ldg(ew + i);
    }
#if __CUDA_ARCH__ >= 900
    cudaTriggerProgrammaticLaunchCompletion();
    cudaGridDependencySynchronize();            // y rows ready
#endif
    if (!act) return;
    const uint4* row = g_yh + (size_t)s * 2;
    uint4 v0 = __ldg(row + 0);
    uint4 v1 = __ldg(row + 1);                  // only .x,.y carry data
    __half2 wh = __float2half2_rn(w);
    unsigned r0 = h2_as_u32(__hmul2(u32_as_h2(v0.x), wh));
    unsigned r1 = h2_as_u32(__hmul2(u32_as_h2(v0.y), wh));
    unsigned r2 = h2_as_u32(__hmul2(u32_as_h2(v0.z), wh));
    unsigned r3 = h2_as_u32(__hmul2(u32_as_h2(v0.w), wh));
    unsigned r4 = h2_as_u32(__hmul2(u32_as_h2(v1.x), wh));
    unsigned r5 = h2_as_u32(__hmul2(u32_as_h2(v1.y), wh));
    unsigned* ag = reinterpret_cast<unsigned*>(g_aggh + (size_t)d * 2);
    red4h2(ag + 0, r0, r1, r2, r3);
    red4h2(ag + 4, r4, r5, 0u, 0u);
}

// ---- K4: pointwise GRU-collapse, 4 threads/node, packed half2 inner loop ----
// PDL prologue: y/dinv/consts are final before the scatter tail (scatter only
// READS y; deg's last reader was dinv_y) — load them and re-zero deg BEFORE the
// gridsync. Only the agg read + agg zero depend on scatter completion.
__global__ void k_final4(float* __restrict__ out, int n) {
    int tid = blockIdx.x * blockDim.x + threadIdx.x;
    int node = tid >> 2;
    int q = tid & 3;                   // channel-quarter 0..3
    bool act = node < n;
    uint4 Y0 = make_uint4(0,0,0,0), Y1 = make_uint4(0,0,0,0);
    float di = 0.f;
    if (act) {
        const uint4* yhp = g_yh + (size_t)node * 2;
        Y0 = __ldg(yhp + 0); Y1 = __ldg(yhp + 1);
        di = g_dinv[node];
        if (q == 2) g_deg[node] = 0.0f;   // deg's last reader (dinv_y) has completed
    }
    __half2 p2[TT / 2];
    #pragma unroll
    for (int t = 0; t < TT / 2; t++) p2[t] = g_p2[t];
#if __CUDA_ARCH__ >= 900
    cudaGridDependencySynchronize();            // agg ready
#endif
    if (!act) return;
    uint4* ahp = g_aggh + (size_t)node * 2;
    uint4 A0 = ahp[0], A1 = ahp[1];
    if (q == 0) ahp[0] = make_uint4(0u, 0u, 0u, 0u);
    else if (q == 1) ahp[1] = make_uint4(0u, 0u, 0u, 0u);
    __half2 dih = __float2half2_rn(di);
    __half2 a2h[TT / 2];
    a2h[0] = __hmul2(dih, __hadd2(u32_as_h2(A0.x), u32_as_h2(Y0.x)));
    a2h[1] = __hmul2(dih, __hadd2(u32_as_h2(A0.y), u32_as_h2(Y0.y)));
    a2h[2] = __hmul2(dih, __hadd2(u32_as_h2(A0.z), u32_as_h2(Y0.z)));
    a2h[3] = __hmul2(dih, __hadd2(u32_as_h2(A0.w), u32_as_h2(Y0.w)));
    a2h[4] = __hmul2(dih, __hadd2(u32_as_h2(A1.x), u32_as_h2(Y1.x)));
    a2h[5] = __hmul2(dih, __hadd2(u32_as_h2(A1.y), u32_as_h2(Y1.y)));
    float acc = 0.f;
    int c0 = q * (CC / 4);
    #pragma unroll
    for (int cc = 0; cc < CC / 4; cc++) {
        int c = c0 + cc;
        __half2 za = g_hz_a[c], zb = g_hz_b[c];
        __half2 ha = g_hh_a[c], hb = g_hh_b[c];
        float hw = g_hw[c];
        __half2 hc2 = __float2half2_rn(0.f);
        #pragma unroll
        for (int t = 0; t < TT / 2; t++) {
            __half2 zarg = __hfma2(a2h[t], za, zb);
            __half2 harg = __hfma2(a2h[t], ha, hb);
            __half2 tz2 = u32_as_h2(tanh2_fast(h2_as_u32(zarg)));   // tanh(zarg/2)
            __half2 th2 = u32_as_h2(tanh2_fast(h2_as_u32(harg)));   // tanh(harg)
            __half2 term = __hsub2(th2, __hmul2(tz2, th2));          // (1-tz)*th
            hc2 = __hfma2(p2[t], term, hc2);
        }
        float hc = __low2float(hc2) + __high2float(hc2);
        acc = fmaf(fmaxf(hc, 0.f), hw, acc);
    }
    // reduce the 4 channel-quarters (lanes q=0..3 of the same node share a warp)
    acc += __shfl_xor_sync(0xFFFFFFFFu, acc, 1);
    acc += __shfl_xor_sync(0xFFFFFFFFu, acc, 2);
    if (q == 0) out[node] = acc + g_hb;
}

extern "C" void kernel_launch(void* const* d_in, const int* in_sizes, int n_in,
                              void* d_out, int out_size) {
    const float* x      = (const float*)d_in[0];
    const int*   ei     = (const int*)  d_in[1];
    const float* ew     = (const float*)d_in[2];
    const float* w_z    = (const float*)d_in[3];
    const float* b_z    = (const float*)d_in[4];
    // d_in[5], d_in[6]: w_r, b_r — reset gate multiplies H=0, unused
    const float* w_h    = (const float*)d_in[7];
    const float* b_h    = (const float*)d_in[8];
    const float* lw_z   = (const float*)d_in[9];
    const float* lb_z   = (const float*)d_in[10];
    // d_in[11], d_in[12]: lw_r, lb_r — unused
    const float* lw_h   = (const float*)d_in[13];
    const float* lb_h   = (const float*)d_in[14];
    const float* att    = (const float*)d_in[15];
    const float* head_w = (const float*)d_in[16];
    const float* head_b = (const float*)d_in[17];
    float* out = (float*)d_out;

    int n = in_sizes[0] / TT;       // x is [N, T]
    int e = in_sizes[2];            // edge_weight is [E]
    if (n > MAXN) n = MAXN;

    const int B = 256;
    int gn  = (n + B - 1) / B;
    int gn4 = (n * 4 + B - 1) / B;
    int degBlocks = ((e + 3) / 4 + B - 1) / B;
    int gsc = (e + B - 1) / B;      // 1 thread per edge

    // first kernel: normal launch
    k_deg_consts<<<degBlocks + 1, B>>>(ei, ew, e, degBlocks,
                                       w_z, b_z, w_h, b_h, lw_z, lb_z, lw_h, lb_h,
                                       att, head_w, head_b);

    // downstream kernels: programmatic dependent launch (overlap launch+prologue)
    cudaLaunchAttribute pdl[1];
    pdl[0].id = cudaLaunchAttributeProgrammaticStreamSerialization;
    pdl[0].val.programmaticStreamSerializationAllowed = 1;

    {
        cudaLaunchConfig_t cfg = {};
        cfg.gridDim = dim3(gn); cfg.blockDim = dim3(B);
        cfg.attrs = pdl; cfg.numAttrs = 1;
        cudaLaunchKernelEx(&cfg, k_dinv_y, x, n);
    }
    {
        cudaLaunchConfig_t cfg = {};
        cfg.gridDim = dim3(gsc); cfg.blockDim = dim3(B);
        cfg.attrs = pdl; cfg.numAttrs = 1;
        cudaLaunchKernelEx(&cfg, k_scatter1, ei, ew, e);
    }
    {
        cudaLaunchConfig_t cfg = {};
        cfg.gridDim = dim3(gn4); cfg.blockDim = dim3(B);
        cfg.attrs = pdl; cfg.numAttrs = 1;
        cudaLaunchKernelEx(&cfg, k_final4, out, n);
    }
}